// round 2
// baseline (speedup 1.0000x reference)
#include <cuda_runtime.h>

// Problem geometry (fixed by reference): tensors [B=64, S=100, K=4, H=32, W=32] fp32.
// Only channel k=3 is used: for each of the 6400 (b,s) pairs, a contiguous run of
// 1024 floats starting at (b*100+s)*4096 + 3*1024.
// result = mean(|convdata[:,:,3] - output[:,:,3]|) over 6400*1024 elements.

static constexpr int NUM_SLICES   = 64 * 100;   // 6400
static constexpr int SLICE_STRIDE = 4 * 32 * 32; // 4096 floats per (b,s)
static constexpr int CH3_OFFSET   = 3 * 32 * 32; // 3072
static constexpr int SLICE_ELEMS  = 32 * 32;     // 1024 floats (= 256 float4)

static constexpr int THREADS = 256;
static constexpr int BLOCKS  = 1600;

__global__ void zero_out_kernel(float* out) {
    out[0] = 0.0f;
}

__global__ __launch_bounds__(THREADS) void abs_diff_mean_kernel(
    const float* __restrict__ a,   // output tensor
    const float* __restrict__ b,   // convdata tensor
    float* __restrict__ res)
{
    const int tid = threadIdx.x;
    float acc = 0.0f;

    // Each block handles slices blockIdx.x, blockIdx.x+gridDim.x, ...
    // Within a slice, thread t reads exactly one float4 (256 threads * 4 = 1024 floats).
    for (int s = blockIdx.x; s < NUM_SLICES; s += gridDim.x) {
        const size_t base = (size_t)s * SLICE_STRIDE + CH3_OFFSET;
        const float4 va = *reinterpret_cast<const float4*>(a + base + tid * 4);
        const float4 vb = *reinterpret_cast<const float4*>(b + base + tid * 4);
        acc += fabsf(vb.x - va.x);
        acc += fabsf(vb.y - va.y);
        acc += fabsf(vb.z - va.z);
        acc += fabsf(vb.w - va.w);
    }

    // Warp reduce
    #pragma unroll
    for (int off = 16; off > 0; off >>= 1)
        acc += __shfl_xor_sync(0xFFFFFFFFu, acc, off);

    __shared__ float warp_sums[THREADS / 32];
    if ((tid & 31) == 0) warp_sums[tid >> 5] = acc;
    __syncthreads();

    if (tid < THREADS / 32) {
        float v = warp_sums[tid];
        #pragma unroll
        for (int off = (THREADS / 64); off > 0; off >>= 1)
            v += __shfl_xor_sync(0xFFu, v, off);
        if (tid == 0) {
            const float inv_total = 1.0f / ((float)NUM_SLICES * (float)SLICE_ELEMS);
            atomicAdd(res, v * inv_total);
        }
    }
}

extern "C" void kernel_launch(void* const* d_in, const int* in_sizes, int n_in,
                              void* d_out, int out_size) {
    const float* out_t  = (const float*)d_in[0];  // "output"
    const float* conv_t = (const float*)d_in[1];  // "convdata"
    float* res = (float*)d_out;

    zero_out_kernel<<<1, 1>>>(res);
    abs_diff_mean_kernel<<<BLOCKS, THREADS>>>(out_t, conv_t, res);
}

// round 3
// speedup vs baseline: 1.2478x; 1.2478x over previous
#include <cuda_runtime.h>

// Tensors [B=64, S=100, K=4, H=32, W=32] fp32; only channel k=3 is read:
// contiguous 1024-float run at s*4096 + 3072 for each of 6400 (b,s) slices.
// result = mean(|convdata[:,:,3] - output[:,:,3]|) over 6400*1024 elements.

static constexpr int NUM_SLICES   = 64 * 100;    // 6400
static constexpr int SLICE_STRIDE = 4 * 32 * 32; // 4096 floats per (b,s)
static constexpr int CH3_OFFSET   = 3 * 32 * 32; // 3072
static constexpr int SLICE_ELEMS  = 32 * 32;     // 1024 floats

static constexpr int THREADS = 256;
static constexpr int SLICES_PER_BLOCK = 4;
static constexpr int BLOCKS  = NUM_SLICES / SLICES_PER_BLOCK;  // 1600

// Cross-block fan-in scratch (device globals: allocation-free).
// Invariant: both are zero at every kernel launch; the last finishing block
// re-zeros them after publishing, so graph replays are deterministic.
__device__ float        g_accum = 0.0f;
__device__ unsigned int g_count = 0u;

__global__ __launch_bounds__(THREADS) void abs_diff_mean_kernel(
    const float* __restrict__ a,   // "output" tensor
    const float* __restrict__ b,   // "convdata" tensor
    float* __restrict__ res)
{
    const int tid = threadIdx.x;
    const int s0  = blockIdx.x * SLICES_PER_BLOCK;

    // Per-slice base offsets (floats); thread t owns one float4 per slice.
    const size_t off = (size_t)tid * 4 + CH3_OFFSET;
    const float4* pa0 = reinterpret_cast<const float4*>(a + (size_t)(s0 + 0) * SLICE_STRIDE + off);
    const float4* pa1 = reinterpret_cast<const float4*>(a + (size_t)(s0 + 1) * SLICE_STRIDE + off);
    const float4* pa2 = reinterpret_cast<const float4*>(a + (size_t)(s0 + 2) * SLICE_STRIDE + off);
    const float4* pa3 = reinterpret_cast<const float4*>(a + (size_t)(s0 + 3) * SLICE_STRIDE + off);
    const float4* pb0 = reinterpret_cast<const float4*>(b + (size_t)(s0 + 0) * SLICE_STRIDE + off);
    const float4* pb1 = reinterpret_cast<const float4*>(b + (size_t)(s0 + 1) * SLICE_STRIDE + off);
    const float4* pb2 = reinterpret_cast<const float4*>(b + (size_t)(s0 + 2) * SLICE_STRIDE + off);
    const float4* pb3 = reinterpret_cast<const float4*>(b + (size_t)(s0 + 3) * SLICE_STRIDE + off);

    // Front-batched loads: 8 independent LDG.128 in flight per thread.
    const float4 a0 = *pa0; const float4 a1 = *pa1;
    const float4 a2 = *pa2; const float4 a3 = *pa3;
    const float4 b0 = *pb0; const float4 b1 = *pb1;
    const float4 b2 = *pb2; const float4 b3 = *pb3;

    float acc;
    acc  = fabsf(b0.x - a0.x) + fabsf(b0.y - a0.y) + fabsf(b0.z - a0.z) + fabsf(b0.w - a0.w);
    acc += fabsf(b1.x - a1.x) + fabsf(b1.y - a1.y) + fabsf(b1.z - a1.z) + fabsf(b1.w - a1.w);
    acc += fabsf(b2.x - a2.x) + fabsf(b2.y - a2.y) + fabsf(b2.z - a2.z) + fabsf(b2.w - a2.w);
    acc += fabsf(b3.x - a3.x) + fabsf(b3.y - a3.y) + fabsf(b3.z - a3.z) + fabsf(b3.w - a3.w);

    // Warp reduce
    #pragma unroll
    for (int off2 = 16; off2 > 0; off2 >>= 1)
        acc += __shfl_xor_sync(0xFFFFFFFFu, acc, off2);

    __shared__ float warp_sums[THREADS / 32];
    if ((tid & 31) == 0) warp_sums[tid >> 5] = acc;
    __syncthreads();

    if (tid == 0) {
        float v = 0.0f;
        #pragma unroll
        for (int w = 0; w < THREADS / 32; w++) v += warp_sums[w];

        atomicAdd(&g_accum, v);
        __threadfence();
        unsigned int done = atomicAdd(&g_count, 1u);
        if (done == (unsigned)(gridDim.x - 1)) {
            // All block partials are visible (fence + atomic ordering).
            float total = atomicExch(&g_accum, 0.0f);   // read + reset scratch
            const float inv_total = 1.0f / ((float)NUM_SLICES * (float)SLICE_ELEMS);
            res[0] = total * inv_total;
            g_count = 0u;                               // reset for next replay
        }
    }
}

extern "C" void kernel_launch(void* const* d_in, const int* in_sizes, int n_in,
                              void* d_out, int out_size) {
    const float* out_t  = (const float*)d_in[0];  // "output"
    const float* conv_t = (const float*)d_in[1];  // "convdata"
    float* res = (float*)d_out;

    abs_diff_mean_kernel<<<BLOCKS, THREADS>>>(out_t, conv_t, res);
}